// round 8
// baseline (speedup 1.0000x reference)
#include <cuda_runtime.h>

#define Bn 128
#define Tn 800
#define Hn 256
#define Kw 10
#define An 64

#define NBLK 128
#define NTH  128
#define BH   (Bn * Hn)

// smem layout (floats)
#define WBUF_FLOATS 4352         // 64 cols x 68 words
#define WT_OFF   0               // 4 bufs = 17408
#define ACT_OFF  17408           // 16 x 644 = 10304
#define ZS_OFF   27712           // 2 x 1024 = 2048
#define ATTN_OFF 29760           // 576
#define SMEM_FLOATS 30336
#define SMEM_BYTES  (SMEM_FLOATS * 4)

#define ACT_STRIDE 644

// ---------------- persistent device state ----------------
// Transposed col-major weights: g_Wt[colp][feat], colp = hu*4+gate.
// act feature layout (shared by slot A):
//   0-2 x(t+1), 3 pad, 4-67 w(t), 68-323 h1(t), 324-579 h2(t-1), 580-582 x(t)
// W1t rows: [x 0-2, pad, w 4-67, h1 68-323, zero 324-383]            (384)
// W2t rows: [zero 0-3, w 4-67, h1 68-323, h2 324-579, x 580-582, 0]  (640)
// W3t rows: [x 0-2, pad, w 4-67, h2 68-323, h3 324-579, 0]           (640)
__device__ float g_W1t[1024 * 384];
__device__ float g_W2t[1024 * 640];
__device__ float g_W3t[1024 * 640];
__device__ float g_b1[1024], g_b2[1024], g_b3[1024];
__device__ float g_Wh[256 * 121];
__device__ float g_bh[121];

__device__ float g_h1[2][BH];
__device__ float g_h2[2][BH];
__device__ float g_c1[BH], g_c2[BH], g_c3[BH];
__device__ float g_w[2][Bn * An];
__device__ float g_kappa[Bn * Kw];
__device__ float g_zero[BH];
__device__ float g_out[Tn * BH];

__device__ unsigned g_bar_cnt = 0;
__device__ volatile unsigned g_bar_gen = 0;

// ---------------- helpers ----------------
__device__ __forceinline__ float sigm(float x) { return 1.0f / (1.0f + __expf(-x)); }
__device__ __forceinline__ float tanh_f(float x) {
    float xx = fminf(15.0f, fmaxf(-15.0f, x));
    float t = __expf(-2.0f * xx);
    return (1.0f - t) / (1.0f + t);
}

__device__ __forceinline__ void grid_barrier() {
    __syncthreads();
    if (threadIdx.x == 0) {
        __threadfence();
        unsigned gen = g_bar_gen;
        if (atomicAdd(&g_bar_cnt, 1u) == NBLK - 1u) {
            atomicSub(&g_bar_cnt, (unsigned)NBLK);
            __threadfence();
            g_bar_gen = gen + 1u;
        } else {
            while (g_bar_gen == gen) { __nanosleep(20); }
            __threadfence();
        }
    }
    __syncthreads();
}

__device__ __forceinline__ void cp16(unsigned d, const float* src) {
    asm volatile("cp.async.ca.shared.global [%0], [%1], 16;" :: "r"(d), "l"(src));
}
__device__ __forceinline__ void cp_commit() {
    asm volatile("cp.async.commit_group;" ::: "memory");
}

// one 64-col x 64-k weight chunk (16KB), cg-path
__device__ __forceinline__ void cp_w(unsigned sm_u32, int buf, const float* __restrict__ Wt,
                                     int kprow, int colp0, int k0) {
    const int tid = threadIdx.x;
    unsigned dst0 = sm_u32 + (unsigned)((WT_OFF + buf * WBUF_FLOATS) * 4);
#pragma unroll
    for (int i = 0; i < 8; i++) {
        int idx = tid + i * NTH;
        int col = idx >> 4;
        int q4 = (idx & 15) << 2;
        const float* src = Wt + (colp0 + col) * kprow + k0 + q4;
        asm volatile("cp.async.cg.shared.global [%0], [%1], 16;"
                     :: "r"(dst0 + (unsigned)((col * 68 + q4) * 4)), "l"(src));
    }
    cp_commit();
}

__device__ __forceinline__ void gemm_chunk(const float* __restrict__ wb,
                                           const float* __restrict__ arb, int arow,
                                           unsigned long long acc[8]) {
#pragma unroll 4
    for (int k2 = 0; k2 < 64; k2 += 4) {
        ulonglong2 wvv = *reinterpret_cast<const ulonglong2*>(wb + k2);
#pragma unroll
        for (int r = 0; r < 8; r++) {
            ulonglong2 av = *reinterpret_cast<const ulonglong2*>(arb + r * ACT_STRIDE + arow + k2);
            asm("fma.rn.f32x2 %0, %1, %2, %0;" : "+l"(acc[r]) : "l"(av.x), "l"(wvv.x));
            asm("fma.rn.f32x2 %0, %1, %2, %0;" : "+l"(acc[r]) : "l"(av.y), "l"(wvv.y));
        }
    }
}

// stage one 256-float-per-batch region (16 bb) via cp.async at feature offset foff
__device__ __forceinline__ void cp_act256(unsigned sm_u32, const float* __restrict__ src,
                                          int b_base, int foff) {
    const int tid = threadIdx.x;
#pragma unroll
    for (int i = 0; i < 8; i++) {
        int idx = tid + i * NTH;
        int bb = idx >> 6, kq = (idx & 63) << 2;
        cp16(sm_u32 + (unsigned)((ACT_OFF + bb * ACT_STRIDE + foff + kq) * 4),
             src + ((b_base + bb) << 8) + kq);
    }
}

// ---------------- slot A: LSTM2(t) + LSTM1(t+1) merged, one act staging ----------------
template <int DO2>
__device__ void slotA(float* sm, unsigned sm_u32, int cta,
                      const float* __restrict__ x, int t_cur, int t_next,
                      const float* __restrict__ wv,
                      const float* __restrict__ h1in,
                      const float* __restrict__ h2prev,
                      float* __restrict__ c1st, float* __restrict__ h1out,
                      float* __restrict__ c2st, float* __restrict__ h2out) {
    const int tid = threadIdx.x;
    const int b_base = (cta >> 4) * 16;
    const int ctile = cta & 15;
    const int colp0 = ctile * 64;
    float* sact = sm + ACT_OFF;
    float* szs  = sm + ZS_OFF;
    const int NC2 = DO2 ? 10 : 0;
    const int NCH = NC2 + 6;

    // prefetch cell states (hides L2 latency behind GEMM)
    const int p0 = tid, p1 = tid + 128;
    const int ix0 = ((b_base + (p0 >> 4)) << 8) + ctile * 16 + (p0 & 15);
    const int ix1 = ((b_base + (p1 >> 4)) << 8) + ctile * 16 + (p1 & 15);
    const float cp1a = c1st[ix0], cp1b = c1st[ix1];
    float cp2a = 0.f, cp2b = 0.f;
    if (DO2) { cp2a = c2st[ix0]; cp2b = c2st[ix1]; }

    // ---- act staging group (must be FIRST committed group) ----
#pragma unroll
    for (int i = 0; i < 2; i++) {       // w: feat 4..67
        int idx = tid + i * NTH;
        int bb = idx >> 4, kq = (idx & 15) << 2;
        cp16(sm_u32 + (unsigned)((ACT_OFF + bb * ACT_STRIDE + 4 + kq) * 4),
             wv + (b_base + bb) * 64 + kq);
    }
    cp_act256(sm_u32, h1in, b_base, 68);
    if (DO2) cp_act256(sm_u32, h2prev, b_base, 324);
    cp_commit();

    // weight chunks 0..2
#pragma unroll
    for (int i = 0; i < 3; i++) {
        if (i < NC2) cp_w(sm_u32, i, g_W2t, 640, colp0, i * 64);
        else         cp_w(sm_u32, i, g_W1t, 384, colp0, (i - NC2) * 64);
    }

    // x scalars (plain; visible by chunk-0 __syncthreads)
    if (tid < 48) {
        int bb = tid / 3, k = tid - bb * 3;
        sact[bb * ACT_STRIDE + k] = x[((b_base + bb) * Tn + t_next) * 3 + k];
    }
    if (DO2 && tid >= 64 && tid < 112) {
        int q = tid - 64, bb = q / 3, k = q - bb * 3;
        sact[bb * ACT_STRIDE + 580 + k] = x[((b_base + bb) * Tn + t_cur) * 3 + k];
    }

    const int cg = tid & 63;
    const int bg = tid >> 6;
    unsigned long long acc2[8], acc1[8];
#pragma unroll
    for (int r = 0; r < 8; r++) { acc2[r] = 0ull; acc1[r] = 0ull; }
    const float* arb = sact + bg * 8 * ACT_STRIDE;

    // W2 chunks
    for (int c = 0; c < NC2; c++) {
        asm volatile("cp.async.wait_group 2;" ::: "memory");
        __syncthreads();
        int nx = c + 3;
        if (nx < NC2)      cp_w(sm_u32, nx & 3, g_W2t, 640, colp0, nx * 64);
        else if (nx < NCH) cp_w(sm_u32, nx & 3, g_W1t, 384, colp0, (nx - NC2) * 64);
        else               cp_commit();
        gemm_chunk(sm + WT_OFF + (c & 3) * WBUF_FLOATS + cg * 68, arb, c * 64, acc2);
    }
    // W1 chunks
    for (int c1i = 0; c1i < 6; c1i++) {
        int c = NC2 + c1i;
        asm volatile("cp.async.wait_group 2;" ::: "memory");
        __syncthreads();
        int nx = c + 3;
        if (nx < NCH) cp_w(sm_u32, nx & 3, g_W1t, 384, colp0, (nx - NC2) * 64);
        else          cp_commit();
        gemm_chunk(sm + WT_OFF + (c & 3) * WBUF_FLOATS + cg * 68, arb, c1i * 64, acc1);
    }

    // zs for both
    if (DO2) {
        float b2 = __ldg(&g_b2[colp0 + cg]);
#pragma unroll
        for (int r = 0; r < 8; r++) {
            float lo, hi;
            asm("mov.b64 {%0, %1}, %2;" : "=f"(lo), "=f"(hi) : "l"(acc2[r]));
            szs[(bg * 8 + r) * 64 + cg] = lo + hi + b2;
        }
    }
    {
        float b1 = __ldg(&g_b1[colp0 + cg]);
#pragma unroll
        for (int r = 0; r < 8; r++) {
            float lo, hi;
            asm("mov.b64 {%0, %1}, %2;" : "=f"(lo), "=f"(hi) : "l"(acc1[r]));
            szs[1024 + (bg * 8 + r) * 64 + cg] = lo + hi + b1;
        }
    }
    __syncthreads();

    // cell updates (2 per thread each LSTM)
    if (DO2) {
        int bl = p0 >> 4, hl = p0 & 15;
        float zi = szs[bl * 64 + hl * 4 + 0], zf = szs[bl * 64 + hl * 4 + 1];
        float zg = szs[bl * 64 + hl * 4 + 2], zo = szs[bl * 64 + hl * 4 + 3];
        float cn = fmaf(sigm(zf), cp2a, sigm(zi) * tanh_f(zg));
        c2st[ix0] = cn; h2out[ix0] = sigm(zo) * tanh_f(cn);
        bl = p1 >> 4; hl = p1 & 15;
        zi = szs[bl * 64 + hl * 4 + 0]; zf = szs[bl * 64 + hl * 4 + 1];
        zg = szs[bl * 64 + hl * 4 + 2]; zo = szs[bl * 64 + hl * 4 + 3];
        cn = fmaf(sigm(zf), cp2b, sigm(zi) * tanh_f(zg));
        c2st[ix1] = cn; h2out[ix1] = sigm(zo) * tanh_f(cn);
    }
    {
        int bl = p0 >> 4, hl = p0 & 15;
        float zi = szs[1024 + bl * 64 + hl * 4 + 0], zf = szs[1024 + bl * 64 + hl * 4 + 1];
        float zg = szs[1024 + bl * 64 + hl * 4 + 2], zo = szs[1024 + bl * 64 + hl * 4 + 3];
        float cn = fmaf(sigm(zf), cp1a, sigm(zi) * tanh_f(zg));
        c1st[ix0] = cn; h1out[ix0] = sigm(zo) * tanh_f(cn);
        bl = p1 >> 4; hl = p1 & 15;
        zi = szs[1024 + bl * 64 + hl * 4 + 0]; zf = szs[1024 + bl * 64 + hl * 4 + 1];
        zg = szs[1024 + bl * 64 + hl * 4 + 2]; zo = szs[1024 + bl * 64 + hl * 4 + 3];
        cn = fmaf(sigm(zf), cp1b, sigm(zi) * tanh_f(zg));
        c1st[ix1] = cn; h1out[ix1] = sigm(zo) * tanh_f(cn);
    }
    __syncthreads();
}

// ---------------- slot B: LSTM3(t) ----------------
__device__ void slotB_lstm3(float* sm, unsigned sm_u32, int cta,
                            const float* __restrict__ x, int t,
                            const float* __restrict__ wv,
                            const float* __restrict__ h2,
                            const float* __restrict__ h3prev,
                            float* __restrict__ c3st, float* __restrict__ hout) {
    const int tid = threadIdx.x;
    const int b_base = (cta >> 4) * 16;
    const int ctile = cta & 15;
    const int colp0 = ctile * 64;
    float* sact = sm + ACT_OFF;
    float* szs  = sm + ZS_OFF;

    const int p0 = tid, p1 = tid + 128;
    const int ix0 = ((b_base + (p0 >> 4)) << 8) + ctile * 16 + (p0 & 15);
    const int ix1 = ((b_base + (p1 >> 4)) << 8) + ctile * 16 + (p1 & 15);
    const float cpa = c3st[ix0], cpb = c3st[ix1];

#pragma unroll
    for (int i = 0; i < 2; i++) {
        int idx = tid + i * NTH;
        int bb = idx >> 4, kq = (idx & 15) << 2;
        cp16(sm_u32 + (unsigned)((ACT_OFF + bb * ACT_STRIDE + 4 + kq) * 4),
             wv + (b_base + bb) * 64 + kq);
    }
    cp_act256(sm_u32, h2, b_base, 68);
    cp_act256(sm_u32, h3prev, b_base, 324);
    cp_commit();

    cp_w(sm_u32, 0, g_W3t, 640, colp0, 0);
    cp_w(sm_u32, 1, g_W3t, 640, colp0, 64);
    cp_w(sm_u32, 2, g_W3t, 640, colp0, 128);

    if (tid < 48) {
        int bb = tid / 3, k = tid - bb * 3;
        sact[bb * ACT_STRIDE + k] = x[((b_base + bb) * Tn + t) * 3 + k];
    }

    const int cg = tid & 63;
    const int bg = tid >> 6;
    unsigned long long acc[8];
#pragma unroll
    for (int r = 0; r < 8; r++) acc[r] = 0ull;
    const float* arb = sact + bg * 8 * ACT_STRIDE;

    for (int c = 0; c < 10; c++) {
        asm volatile("cp.async.wait_group 2;" ::: "memory");
        __syncthreads();
        if (c + 3 < 10) cp_w(sm_u32, (c + 3) & 3, g_W3t, 640, colp0, (c + 3) * 64);
        else            cp_commit();
        gemm_chunk(sm + WT_OFF + (c & 3) * WBUF_FLOATS + cg * 68, arb, c * 64, acc);
    }

    float bias = __ldg(&g_b3[colp0 + cg]);
#pragma unroll
    for (int r = 0; r < 8; r++) {
        float lo, hi;
        asm("mov.b64 {%0, %1}, %2;" : "=f"(lo), "=f"(hi) : "l"(acc[r]));
        szs[(bg * 8 + r) * 64 + cg] = lo + hi + bias;
    }
    __syncthreads();

    {
        int bl = p0 >> 4, hl = p0 & 15;
        float zi = szs[bl * 64 + hl * 4 + 0], zf = szs[bl * 64 + hl * 4 + 1];
        float zg = szs[bl * 64 + hl * 4 + 2], zo = szs[bl * 64 + hl * 4 + 3];
        float cn = fmaf(sigm(zf), cpa, sigm(zi) * tanh_f(zg));
        c3st[ix0] = cn; hout[ix0] = sigm(zo) * tanh_f(cn);
        bl = p1 >> 4; hl = p1 & 15;
        zi = szs[bl * 64 + hl * 4 + 0]; zf = szs[bl * 64 + hl * 4 + 1];
        zg = szs[bl * 64 + hl * 4 + 2]; zo = szs[bl * 64 + hl * 4 + 3];
        cn = fmaf(sigm(zf), cpb, sigm(zi) * tanh_f(zg));
        c3st[ix1] = cn; hout[ix1] = sigm(zo) * tanh_f(cn);
    }
    __syncthreads();
}

// ---------------- attention: 1 batch per CTA ----------------
__device__ void attn_tile(float* sm, int b, const float* __restrict__ h1,
                          float* __restrict__ wout,
                          const int* __restrict__ cidx,
                          const float* __restrict__ Ww,
                          const float* __restrict__ bw) {
    float* hrow = sm + ATTN_OFF;
    float* aw   = hrow + 256;
    float* kap  = aw + 32;
    float* phi  = kap + 16;
    int*   cs   = (int*)(phi + 64);
    float* part = (float*)(cs + 64);
    const int tt = threadIdx.x;

    hrow[tt] = h1[(b << 8) + tt];
    hrow[tt + 128] = h1[(b << 8) + tt + 128];
    if (tt < 64) cs[tt] = __ldg(&cidx[b * 64 + tt]);
    __syncthreads();

    if (tt < 120) {
        int j = tt % 30, p = tt / 30;
        float z = 0.0f;
        const float* wp = Ww + (p * 64) * 30 + j;
        const float* hp = hrow + p * 64;
#pragma unroll 8
        for (int i = 0; i < 64; i++)
            z = fmaf(hp[i], __ldg(&wp[i * 30]), z);
        part[p * 30 + j] = z;
    }
    __syncthreads();

    if (tt < 30) {
        float z = __ldg(&bw[tt]) + part[tt] + part[30 + tt] + part[60 + tt] + part[90 + tt];
        aw[tt] = __expf(z);
    }
    __syncthreads();

    if (tt < 10) {
        float kn = fmaf(0.1f, aw[20 + tt], g_kappa[b * 10 + tt]);
        g_kappa[b * 10 + tt] = kn;
        kap[tt] = kn;
    }
    __syncthreads();

    if (tt < 64) {
        float uu = (float)tt, ph = 0.0f;
#pragma unroll
        for (int k = 0; k < 10; k++) {
            float d = kap[k] - uu;
            ph = fmaf(aw[k], __expf(-aw[10 + k] * d * d), ph);
        }
        phi[tt] = ph;
    }
    __syncthreads();

    if (tt < 64) {
        float s = 0.0f;
        for (int u = 0; u < 64; u++)
            if (cs[u] == tt) s += phi[u];
        wout[b * 64 + tt] = s;
    }
    __syncthreads();
}

// ---------------- persistent RNN kernel ----------------
__global__ void __launch_bounds__(NTH)
rnn_kernel(const float* __restrict__ x, const int* __restrict__ cidx,
           const float* __restrict__ Ww, const float* __restrict__ bw) {
    extern __shared__ float sm[];
    unsigned sm_u32 = (unsigned)__cvta_generic_to_shared(sm);
    const int cta = blockIdx.x;
    const int tid = threadIdx.x;

    for (int i = tid; i < 16 * ACT_STRIDE; i += NTH) sm[ACT_OFF + i] = 0.0f;

    {
        int g0 = cta * NTH + tid;
        int gsz = NBLK * NTH;
        for (int p = g0; p < BH; p += gsz) {
            g_h1[0][p] = 0.f; g_h1[1][p] = 0.f;
            g_h2[0][p] = 0.f; g_h2[1][p] = 0.f;
            g_c1[p] = 0.f; g_c2[p] = 0.f; g_c3[p] = 0.f;
            g_zero[p] = 0.f;
        }
        for (int p = g0; p < Bn * An; p += gsz) { g_w[0][p] = 0.f; g_w[1][p] = 1.0f; }
        for (int p = g0; p < Bn * Kw; p += gsz) g_kappa[p] = 0.f;
    }
    grid_barrier();

    // prologue: LSTM1(0) with w(-1)=ones, h1(-1)=0
    slotA<0>(sm, sm_u32, cta, x, 0, 0, g_w[1], g_h1[1], (const float*)0,
             g_c1, g_h1[0], (float*)0, (float*)0);
    grid_barrier();
    attn_tile(sm, cta, g_h1[0], g_w[0], cidx, Ww, bw);
    grid_barrier();

    for (int t = 0; t < Tn; t++) {
        const int p = t & 1, pn = (t + 1) & 1;
        const int tnext = (t + 1 < Tn) ? (t + 1) : t;

        slotA<1>(sm, sm_u32, cta, x, t, tnext, g_w[p], g_h1[p], g_h2[pn],
                 g_c1, g_h1[pn], g_c2, g_h2[p]);
        grid_barrier();

        slotB_lstm3(sm, sm_u32, cta, x, t, g_w[p], g_h2[p],
                    (t > 0) ? (g_out + (t - 1) * BH) : g_zero,
                    g_c3, g_out + t * BH);
        if (t + 1 < Tn)
            attn_tile(sm, cta, g_h1[pn], g_w[pn], cidx, Ww, bw);
        grid_barrier();
    }
}

__global__ void noop_kernel() {}

// ---------------- weight pre-pack ----------------
__global__ void prep_kernel(
    const float* Wih1, const float* Whh1, const float* bih1, const float* bhh1,
    const float* Wih2, const float* Whh2, const float* bih2, const float* bhh2,
    const float* Wih3, const float* Whh3, const float* bih3, const float* bhh3,
    const float* We, const float* be, const float* Wpi, const float* bpi,
    const float* Wmu1, const float* bmu1, const float* Wmu2, const float* bmu2,
    const float* Ws1, const float* bs1, const float* Ws2, const float* bs2,
    const float* Wrho, const float* brho) {
    int g0 = blockIdx.x * blockDim.x + threadIdx.x;
    int gsz = gridDim.x * blockDim.x;

    // W1t: x@0-2, pad, w@4-67, h1@68-323, zero pad
    for (int pidx = g0; pidx < 1024 * 384; pidx += gsz) {
        int colp = pidx / 384, feat = pidx - colp * 384;
        int hu = colp >> 2, g = colp & 3;
        int j = g * 256 + hu;
        float v = 0.f;
        if (feat < 3)        v = Wih1[feat * 1024 + j];
        else if (feat == 3)  v = 0.f;
        else if (feat < 68)  v = Wih1[(feat - 1) * 1024 + j];
        else if (feat < 324) v = Whh1[(feat - 68) * 1024 + j];
        g_W1t[pidx] = v;
    }
    // W2t: zero@0-3, w@4-67, h1@68-323, h2@324-579, x@580-582 ; W3t: x@0-2, w@4-67, h2@68-323, h3@324-579
    for (int pidx = g0; pidx < 1024 * 640; pidx += gsz) {
        int colp = pidx / 640, feat = pidx - colp * 640;
        int hu = colp >> 2, g = colp & 3;
        int j = g * 256 + hu;
        float v2 = 0.f, v3 = 0.f;
        if (feat < 3)                        v3 = Wih3[feat * 1024 + j];
        if (feat >= 4 && feat < 324) {
            v2 = Wih2[(feat - 1) * 1024 + j];
            v3 = Wih3[(feat - 1) * 1024 + j];
        } else if (feat >= 324 && feat < 580) {
            v2 = Whh2[(feat - 324) * 1024 + j];
            v3 = Whh3[(feat - 324) * 1024 + j];
        } else if (feat >= 580 && feat < 583) {
            v2 = Wih2[(feat - 580) * 1024 + j];
        }
        g_W2t[pidx] = v2;
        g_W3t[pidx] = v3;
    }
    for (int colp = g0; colp < 1024; colp += gsz) {
        int hu = colp >> 2, g = colp & 3;
        int j = g * 256 + hu;
        g_b1[colp] = bih1[j] + bhh1[j];
        g_b2[colp] = bih2[j] + bhh2[j];
        g_b3[colp] = bih3[j] + bhh3[j];
    }
    for (int pidx = g0; pidx < 256 * 121; pidx += gsz) {
        int i = pidx / 121, col = pidx - i * 121;
        float v;
        if (col == 0)       v = We[i];
        else if (col < 21)  v = Wpi[i * 20 + (col - 1)];
        else if (col < 41)  v = Wmu1[i * 20 + (col - 21)];
        else if (col < 61)  v = Wmu2[i * 20 + (col - 41)];
        else if (col < 81)  v = Ws1[i * 20 + (col - 61)];
        else if (col < 101) v = Ws2[i * 20 + (col - 81)];
        else                v = Wrho[i * 20 + (col - 101)];
        g_Wh[pidx] = v;
    }
    for (int col = g0; col < 121; col += gsz) {
        float v;
        if (col == 0)       v = be[0];
        else if (col < 21)  v = bpi[col - 1];
        else if (col < 41)  v = bmu1[col - 21];
        else if (col < 61)  v = bmu2[col - 41];
        else if (col < 81)  v = bs1[col - 61];
        else if (col < 101) v = bs2[col - 81];
        else                v = brho[col - 101];
        g_bh[col] = v;
    }
}

// ---------------- MDN heads ----------------
__global__ void __launch_bounds__(128)
heads_kernel(float* __restrict__ out) {
    __shared__ __align__(16) float hs[32 * 256];
    __shared__ float pz[32][20];
    const int r0 = blockIdx.x * 32;
    const int tid = threadIdx.x;

    {
        const float4* src = reinterpret_cast<const float4*>(g_out + r0 * 256);
        float4* dst = reinterpret_cast<float4*>(hs);
        for (int pidx = tid; pidx < 32 * 64; pidx += 128) dst[pidx] = src[pidx];
    }
    __syncthreads();

    const int j = tid;
    float acc[32];
    if (j < 121) {
#pragma unroll
        for (int r = 0; r < 32; r++) acc[r] = 0.0f;
#pragma unroll 2
        for (int i4 = 0; i4 < 64; i4++) {
            float w0 = g_Wh[(i4 * 4 + 0) * 121 + j];
            float w1 = g_Wh[(i4 * 4 + 1) * 121 + j];
            float w2 = g_Wh[(i4 * 4 + 2) * 121 + j];
            float w3 = g_Wh[(i4 * 4 + 3) * 121 + j];
#pragma unroll
            for (int r = 0; r < 32; r++) {
                float4 hv = reinterpret_cast<const float4*>(hs + r * 256)[i4];
                acc[r] = fmaf(hv.x, w0, fmaf(hv.y, w1, fmaf(hv.z, w2, fmaf(hv.w, w3, acc[r]))));
            }
        }
        float bias = g_bh[j];
#pragma unroll
        for (int r = 0; r < 32; r++) acc[r] += bias;
        if (j >= 1 && j < 21)
            for (int r = 0; r < 32; r++) pz[r][j - 1] = acc[r];
    }
    __syncthreads();

    if (j < 121) {
        const int TB = Tn * Bn;
        float* es  = out;
        float* pi  = out + TB;
        float* mu1 = out + TB + TB * 20;
        float* mu2 = mu1 + TB * 20;
        float* s1  = mu2 + TB * 20;
        float* s2  = s1 + TB * 20;
        float* rh  = s2 + TB * 20;
        for (int r = 0; r < 32; r++) {
            int gr = r0 + r;
            float z = acc[r];
            if (j == 0) {
                es[gr] = 1.0f / (1.0f + __expf(z));
            } else if (j < 21) {
                float m = -1e30f;
                for (int k = 0; k < 20; k++) m = fmaxf(m, pz[r][k]);
                float s = 0.f;
                for (int k = 0; k < 20; k++) s += __expf(pz[r][k] - m);
                pi[gr * 20 + (j - 1)] = __expf(z - m) / s;
            } else if (j < 41) {
                mu1[gr * 20 + (j - 21)] = z;
            } else if (j < 61) {
                mu2[gr * 20 + (j - 41)] = z;
            } else if (j < 81) {
                s1[gr * 20 + (j - 61)] = __expf(z);
            } else if (j < 101) {
                s2[gr * 20 + (j - 81)] = __expf(z);
            } else {
                rh[gr * 20 + (j - 101)] = tanh_f(z);
            }
        }
    }
}

// ---------------- launch ----------------
extern "C" void kernel_launch(void* const* d_in, const int* in_sizes, int n_in,
                              void* d_out, int out_size) {
    const float* x    = (const float*)d_in[0];
    const int*   c    = (const int*)d_in[1];
    const float* Wih1 = (const float*)d_in[2];
    const float* Whh1 = (const float*)d_in[3];
    const float* bih1 = (const float*)d_in[4];
    const float* bhh1 = (const float*)d_in[5];
    const float* Wih2 = (const float*)d_in[6];
    const float* Whh2 = (const float*)d_in[7];
    const float* bih2 = (const float*)d_in[8];
    const float* bhh2 = (const float*)d_in[9];
    const float* Wih3 = (const float*)d_in[10];
    const float* Whh3 = (const float*)d_in[11];
    const float* bih3 = (const float*)d_in[12];
    const float* bhh3 = (const float*)d_in[13];
    const float* Ww   = (const float*)d_in[14];
    const float* bw   = (const float*)d_in[15];
    const float* We   = (const float*)d_in[16];
    const float* be   = (const float*)d_in[17];
    const float* Wpi  = (const float*)d_in[18];
    const float* bpi  = (const float*)d_in[19];
    const float* Wmu1 = (const float*)d_in[20];
    const float* bmu1 = (const float*)d_in[21];
    const float* Wmu2 = (const float*)d_in[22];
    const float* bmu2 = (const float*)d_in[23];
    const float* Ws1  = (const float*)d_in[24];
    const float* bs1  = (const float*)d_in[25];
    const float* Ws2  = (const float*)d_in[26];
    const float* bs2  = (const float*)d_in[27];
    const float* Wrho = (const float*)d_in[28];
    const float* brho = (const float*)d_in[29];

    cudaFuncSetAttribute(rnn_kernel, cudaFuncAttributeMaxDynamicSharedMemorySize,
                         SMEM_BYTES);

    prep_kernel<<<512, 256>>>(Wih1, Whh1, bih1, bhh1,
                              Wih2, Whh2, bih2, bhh2,
                              Wih3, Whh3, bih3, bhh3,
                              We, be, Wpi, bpi, Wmu1, bmu1, Wmu2, bmu2,
                              Ws1, bs1, Ws2, bs2, Wrho, brho);
    noop_kernel<<<1, 32>>>();
    noop_kernel<<<1, 32>>>();
    rnn_kernel<<<NBLK, NTH, SMEM_BYTES>>>(x, c, Ww, bw);
    heads_kernel<<<(Tn * Bn) / 32, 128>>>((float*)d_out);
}